// round 3
// baseline (speedup 1.0000x reference)
#include <cuda_runtime.h>
#include <math.h>

// Problem constants
constexpr int B_   = 64;
constexpr int L_   = 512;
constexpr int DQ_  = 2048;
constexpr int H_   = 128;
constexpr int K_   = 128;
constexpr int DC_  = 512;
constexpr int DCQ_ = 1536;
constexpr int R_   = 64;
constexpr int HK_  = H_ * K_;      // 16384
constexpr int SPLITS = 8;

// ---------------- scratch (no cudaMalloc allowed) ----------------
__device__ float g_sin[L_ * DC_];
__device__ float g_cos[L_ * DC_];
__device__ float g_kv[B_ * L_ * DC_];      // roped kv
__device__ float g_S[B_ * DC_];            // sum over l of kv
__device__ float g_qhk[B_ * HK_];          // [B, H*K]
__device__ float g_W2[H_ * K_ * R_];       // fused w_kc_q @ W_qr per head
__device__ float g_qr[B_ * H_ * R_];       // [B, H, R]
__device__ float g_scores[B_ * H_ * DC_];  // scores -> attn (in place)
__device__ float g_ctx[B_ * H_ * DC_];     // ctx_c
__device__ float g_lat[B_ * HK_];          // ctx_lat
__device__ float g_split[SPLITS * B_ * DQ_];

// ---------------- RoPE tables ----------------
__global__ void rope_table_kernel() {
    int idx = blockIdx.x * 256 + threadIdx.x;      // L*DC = 262144
    int l = idx / DC_;
    int d = idx % DC_;
    float expo = (float)(d & ~1) / (float)DC_;     // 2*(d/2)/DC
    float invf = expf(-expo * 9.210340371976184f); // ln(10000)
    float ang = (float)l * invf;
    g_sin[idx] = sinf(ang);
    g_cos[idx] = cosf(ang);
}

// ---------------- RoPE + column sum S ----------------
__global__ void rope_kernel(const float* __restrict__ kv_c) {
    int d = blockIdx.x * 128 + threadIdx.x;
    int b = blockIdx.y;
    const float* src = kv_c + (long)b * L_ * DC_;
    float* dst = g_kv + (long)b * L_ * DC_;
    int d2 = (d < DC_ / 2) ? d + DC_ / 2 : d - DC_ / 2;
    float sign = (d < DC_ / 2) ? -1.f : 1.f;
    float s = 0.f;
    for (int l = 0; l < L_; l++) {
        float x = src[l * DC_ + d];
        float y = src[l * DC_ + d2];
        float v = x * g_cos[l * DC_ + d] + sign * y * g_sin[l * DC_ + d];
        dst[l * DC_ + d] = v;
        s += v;
    }
    g_S[b * DC_ + d] = s;
}

// ---------------- generic tiled batched SGEMM ----------------
// C[z][M,N] = A[z][M,Kd] * B[z]   with B either [N,Kd] (TRANSB) or [Kd,N].
// All of M % 64 == 0, N % 64 == 0, Kd % 16 == 0 by construction.
template <bool TRANSB>
__global__ void __launch_bounds__(256) gemm_kernel(
    const float* __restrict__ A, const float* __restrict__ Bm, float* __restrict__ C,
    int M, int N, int Kd, int lda, int ldb, int ldc,
    long sA, long sB, long sC)
{
    constexpr int BM = 64, BN = 64, BK = 16;
    __shared__ float As[BK][BM];
    __shared__ float Bs[BK][BN];

    const float* Ab = A + (long)blockIdx.z * sA + (long)blockIdx.y * BM * lda;
    const float* Bb = Bm + (long)blockIdx.z * sB;
    float* Cb = C + (long)blockIdx.z * sC + (long)blockIdx.y * BM * ldc + blockIdx.x * BN;
    const int nBase = blockIdx.x * BN;

    const int tid = threadIdx.x;
    const int tx = tid & 15;   // n group
    const int ty = tid >> 4;   // m group

    float acc[4][4] = {};

    for (int k0 = 0; k0 < Kd; k0 += BK) {
        // A tile: 64 rows x 16 k
        #pragma unroll
        for (int it = 0; it < 4; it++) {
            int m = (tid >> 4) + it * 16;
            int k = tid & 15;
            As[k][m] = Ab[(long)m * lda + k0 + k];
        }
        if (TRANSB) {
            #pragma unroll
            for (int it = 0; it < 4; it++) {
                int n = (tid >> 4) + it * 16;
                int k = tid & 15;
                Bs[k][n] = Bb[(long)(nBase + n) * ldb + k0 + k];
            }
        } else {
            #pragma unroll
            for (int it = 0; it < 4; it++) {
                int k = (tid >> 6) + it * 4;
                int n = tid & 63;
                Bs[k][n] = Bb[(long)(k0 + k) * ldb + nBase + n];
            }
        }
        __syncthreads();

        #pragma unroll
        for (int kk = 0; kk < BK; kk++) {
            float4 a4 = *reinterpret_cast<const float4*>(&As[kk][ty * 4]);
            float4 b4 = *reinterpret_cast<const float4*>(&Bs[kk][tx * 4]);
            float a[4] = {a4.x, a4.y, a4.z, a4.w};
            float b[4] = {b4.x, b4.y, b4.z, b4.w};
            #pragma unroll
            for (int i = 0; i < 4; i++)
                #pragma unroll
                for (int j = 0; j < 4; j++)
                    acc[i][j] += a[i] * b[j];
        }
        __syncthreads();
    }

    #pragma unroll
    for (int i = 0; i < 4; i++)
        #pragma unroll
        for (int j = 0; j < 4; j++)
            Cb[(long)(ty * 4 + i) * ldc + tx * 4 + j] = acc[i][j];
}

// ---------------- softmax over d (with S scaling folded in) ----------------
__device__ __forceinline__ float warpMaxf(float v) {
    #pragma unroll
    for (int o = 16; o > 0; o >>= 1) v = fmaxf(v, __shfl_xor_sync(0xffffffffu, v, o));
    return v;
}
__device__ __forceinline__ float warpSumf(float v) {
    #pragma unroll
    for (int o = 16; o > 0; o >>= 1) v += __shfl_xor_sync(0xffffffffu, v, o);
    return v;
}

__global__ void softmax_kernel() {
    int bh = blockIdx.x;
    int b = bh >> 7;                       // / H_
    float* row = g_scores + (long)bh * DC_;
    const float* Sb = g_S + b * DC_;
    int tid = threadIdx.x;                 // 128
    int lane = tid & 31, wid = tid >> 5;

    float v[4];
    float mx = -3.4e38f;
    #pragma unroll
    for (int i = 0; i < 4; i++) {
        int d = tid + i * 128;
        v[i] = row[d] * Sb[d];
        mx = fmaxf(mx, v[i]);
    }
    mx = warpMaxf(mx);
    __shared__ float sm[4], ss[4];
    if (lane == 0) sm[wid] = mx;
    __syncthreads();
    mx = fmaxf(fmaxf(sm[0], sm[1]), fmaxf(sm[2], sm[3]));

    float sum = 0.f;
    #pragma unroll
    for (int i = 0; i < 4; i++) {
        v[i] = expf(v[i] - mx);
        sum += v[i];
    }
    sum = warpSumf(sum);
    if (lane == 0) ss[wid] = sum;
    __syncthreads();
    sum = ss[0] + ss[1] + ss[2] + ss[3];
    float inv = 1.0f / sum;
    #pragma unroll
    for (int i = 0; i < 4; i++)
        row[tid + i * 128] = v[i] * inv;
}

// ---------------- split-K reduction for final GEMM ----------------
__global__ void reduce_split_kernel(float* __restrict__ out) {
    int i = blockIdx.x * 256 + threadIdx.x;   // B*DQ = 131072
    float s = 0.f;
    #pragma unroll
    for (int sp = 0; sp < SPLITS; sp++)
        s += g_split[(long)sp * (B_ * DQ_) + i];
    out[i] = s;
}

// ---------------- launch ----------------
extern "C" void kernel_launch(void* const* d_in, const int* in_sizes, int n_in,
                              void* d_out, int out_size) {
    const float* hidden_q   = (const float*)d_in[0];   // [B, DQ]
    const float* kv_c       = (const float*)d_in[1];   // [B, L, DC]
    const float* q_proj_w   = (const float*)d_in[2];   // [H*K, DQ]
    const float* w_kc_q     = (const float*)d_in[3];   // [H, K, DCQ]
    const float* w_kc_kv    = (const float*)d_in[4];   // [H, K, DC]
    const float* W_qr       = (const float*)d_in[5];   // [H, DCQ, R]
    const float* W_kr       = (const float*)d_in[6];   // [H, DC, R]
    const float* out_proj_w = (const float*)d_in[7];   // [DQ, H*K]
    float* out = (float*)d_out;

    float *p_kv, *p_qhk, *p_W2, *p_qr, *p_sc, *p_ctx, *p_lat, *p_split;
    cudaGetSymbolAddress((void**)&p_kv,    g_kv);
    cudaGetSymbolAddress((void**)&p_qhk,   g_qhk);
    cudaGetSymbolAddress((void**)&p_W2,    g_W2);
    cudaGetSymbolAddress((void**)&p_qr,    g_qr);
    cudaGetSymbolAddress((void**)&p_sc,    g_scores);
    cudaGetSymbolAddress((void**)&p_ctx,   g_ctx);
    cudaGetSymbolAddress((void**)&p_lat,   g_lat);
    cudaGetSymbolAddress((void**)&p_split, g_split);

    // 1. RoPE tables, then RoPE + S reduction
    rope_table_kernel<<<(L_ * DC_) / 256, 256>>>();
    rope_kernel<<<dim3(DC_ / 128, B_), 128>>>(kv_c);

    // 2. q_hk = hidden_q @ q_proj_w^T        [64, 16384]
    gemm_kernel<true><<<dim3(HK_ / 64, 1, 1), 256>>>(
        hidden_q, q_proj_w, p_qhk,
        B_, HK_, DQ_, DQ_, DQ_, HK_, 0, 0, 0);

    // 3. W2[h] = w_kc_q[h] @ W_qr[h]         [128, 64] per head (NN)
    gemm_kernel<false><<<dim3(1, 2, H_), 256>>>(
        w_kc_q, W_qr, p_W2,
        K_, R_, DCQ_, DCQ_, R_, R_,
        (long)K_ * DCQ_, (long)DCQ_ * R_, (long)K_ * R_);

    // 4. q_r[b,h,:] = q_hk[b,h,:] @ W2[h]    [64, 64] per head (NN)
    gemm_kernel<false><<<dim3(1, 1, H_), 256>>>(
        p_qhk, p_W2, p_qr,
        B_, R_, K_, HK_, R_, H_ * R_,
        (long)K_, (long)K_ * R_, (long)R_);

    // 5. T[b,h,d] = q_r[b,h,:] . W_kr[h,d,:] [64, 512] per head (NT) -> scores
    gemm_kernel<true><<<dim3(DC_ / 64, 1, H_), 256>>>(
        p_qr, W_kr, p_sc,
        B_, DC_, R_, H_ * R_, R_, H_ * DC_,
        (long)R_, (long)DC_ * R_, (long)DC_);

    // 6. softmax over d, with scores *= S[b,d] folded in (attn in place)
    softmax_kernel<<<B_ * H_, 128>>>();

    // 7. ctx_c[b] = attn[b] @ kv[b]          [128, 512] per batch (NN)
    gemm_kernel<false><<<dim3(DC_ / 64, H_ / 64, B_), 256>>>(
        p_sc, p_kv, p_ctx,
        H_, DC_, L_, DC_, DC_, DC_,
        (long)H_ * DC_, (long)L_ * DC_, (long)H_ * DC_);

    // 8. ctx_lat[b,h,:] = ctx_c[b,h,:] @ w_kc_kv[h]^T  [64, 128] per head (NT)
    gemm_kernel<true><<<dim3(K_ / 64, 1, H_), 256>>>(
        p_ctx, w_kc_kv, p_lat,
        B_, K_, DC_, H_ * DC_, DC_, HK_,
        (long)DC_, (long)K_ * DC_, (long)K_);

    // 9. out = ctx_lat @ out_proj_w^T  — deterministic split-K (8 chunks of 2048)
    gemm_kernel<true><<<dim3(DQ_ / 64, 1, SPLITS), 256>>>(
        p_lat, out_proj_w, p_split,
        B_, DQ_, HK_ / SPLITS, HK_, HK_, DQ_,
        (long)(HK_ / SPLITS), (long)(HK_ / SPLITS), (long)B_ * DQ_);

    reduce_split_kernel<<<(B_ * DQ_) / 256, 256>>>(out);
}

// round 7
// speedup vs baseline: 1.1224x; 1.1224x over previous
#include <cuda_runtime.h>
#include <math.h>

// Problem constants
constexpr int B_   = 64;
constexpr int L_   = 512;
constexpr int DQ_  = 2048;
constexpr int H_   = 128;
constexpr int K_   = 128;
constexpr int DC_  = 512;
constexpr int DCQ_ = 1536;
constexpr int R_   = 64;
constexpr int HK_  = H_ * K_;      // 16384
constexpr int SPLITS = 16;

typedef unsigned long long u64;

// ---------------- scratch (no cudaMalloc allowed) ----------------
__device__ float g_sin[L_ * DC_];
__device__ float g_cos[L_ * DC_];
__device__ float g_kv[B_ * L_ * DC_];      // roped kv
__device__ float g_S[B_ * DC_];            // sum over l of kv
__device__ float g_qhk[B_ * HK_];          // [B, H*K]
__device__ float g_W2[H_ * K_ * R_];       // fused w_kc_q @ W_qr per head
__device__ float g_qr[B_ * H_ * R_];       // [B, H, R]
__device__ float g_scores[B_ * H_ * DC_];  // scores -> attn (in place)
__device__ float g_ctx[B_ * H_ * DC_];     // ctx_c
__device__ float g_lat[B_ * HK_];          // ctx_lat
__device__ float g_split[SPLITS * B_ * DQ_];

// ---------------- f32x2 packed helpers ----------------
__device__ __forceinline__ u64 pack2(float lo, float hi) {
    u64 r; asm("mov.b64 %0, {%1, %2};" : "=l"(r) : "f"(lo), "f"(hi)); return r;
}
__device__ __forceinline__ void ffma2(u64& d, u64 a, u64 b) {
    asm("fma.rn.f32x2 %0, %1, %2, %0;" : "+l"(d) : "l"(a), "l"(b));
}

// ---------------- RoPE tables ----------------
__global__ void rope_table_kernel() {
    int idx = blockIdx.x * 256 + threadIdx.x;      // L*DC = 262144
    int l = idx / DC_;
    int d = idx % DC_;
    float expo = (float)(d & ~1) / (float)DC_;     // 2*(d/2)/DC
    float invf = expf(-expo * 9.210340371976184f); // ln(10000)
    float ang = (float)l * invf;
    g_sin[idx] = sinf(ang);
    g_cos[idx] = cosf(ang);
}

// ---------------- RoPE + column sum S ----------------
__global__ void rope_kernel(const float* __restrict__ kv_c) {
    int d = blockIdx.x * 128 + threadIdx.x;
    int b = blockIdx.y;
    const float* src = kv_c + (long)b * L_ * DC_;
    float* dst = g_kv + (long)b * L_ * DC_;
    int d2 = (d < DC_ / 2) ? d + DC_ / 2 : d - DC_ / 2;
    float sign = (d < DC_ / 2) ? -1.f : 1.f;
    float s = 0.f;
    for (int l = 0; l < L_; l++) {
        float x = src[l * DC_ + d];
        float y = src[l * DC_ + d2];
        float v = x * g_cos[l * DC_ + d] + sign * y * g_sin[l * DC_ + d];
        dst[l * DC_ + d] = v;
        s += v;
    }
    g_S[b * DC_ + d] = s;
}

// ---------------- tiled batched SGEMM with packed f32x2 FMA ----------------
// C[z][M,N] = A[z][M,Kd] * B[z]   with B either [N,Kd] (TRANSB) or [Kd,N].
// BM=64 fixed, BN in {64,128}, 256 threads, thread microtile 4 x TN (TN=BN/16).
// Requirements (all hold by construction): M%64==0, N%BN==0, Kd%16==0,
// lda/ldb/ldc even, all base pointers 16B aligned.
template <int BN, bool TRANSB>
__global__ void __launch_bounds__(256) gemm2_kernel(
    const float* __restrict__ A, const float* __restrict__ Bm, float* __restrict__ C,
    int M, int N, int Kd, int lda, int ldb, int ldc,
    long sA, long sB, long sC)
{
    constexpr int BM = 64, BK = 16;
    constexpr int TN = BN / 16;     // 8 or 4
    constexpr int TNH = TN / 2;     // f32x2 pairs per row

    __shared__ float As[BK][BM];
    __shared__ float Bs[BK][BN];

    const int tid = threadIdx.x;
    const int tx = tid & 15;        // n group (TN columns each)
    const int ty = tid >> 4;        // m group (4 rows each)

    const float* Ab = A + (long)blockIdx.z * sA + (long)blockIdx.y * BM * lda;
    const float* Bb = Bm + (long)blockIdx.z * sB;
    const int nBase = blockIdx.x * BN;
    float* Cb = C + (long)blockIdx.z * sC + (long)blockIdx.y * BM * ldc + nBase;

    // A tile load mapping: 64 rows x 16 k = 256 float4
    const int am  = tid >> 2;        // 0..63
    const int akq = (tid & 3) * 4;   // 0,4,8,12

    u64 acc[4][TNH];
    #pragma unroll
    for (int i = 0; i < 4; i++)
        #pragma unroll
        for (int j = 0; j < TNH; j++) acc[i][j] = 0ull;

    for (int k0 = 0; k0 < Kd; k0 += BK) {
        // ---- A tile (transpose to As[k][m]) ----
        {
            float4 av = *reinterpret_cast<const float4*>(&Ab[(long)am * lda + k0 + akq]);
            As[akq + 0][am] = av.x;
            As[akq + 1][am] = av.y;
            As[akq + 2][am] = av.z;
            As[akq + 3][am] = av.w;
        }
        // ---- B tile ----
        if (TRANSB) {
            // B rows along k contiguous: BN rows x 16 k
            #pragma unroll
            for (int it = 0; it < BN / 64; it++) {
                int n = (tid >> 2) + it * 64;
                float4 bv = *reinterpret_cast<const float4*>(
                    &Bb[(long)(nBase + n) * ldb + k0 + akq]);
                Bs[akq + 0][n] = bv.x;
                Bs[akq + 1][n] = bv.y;
                Bs[akq + 2][n] = bv.z;
                Bs[akq + 3][n] = bv.w;
            }
        } else {
            // B rows along n contiguous: 16 k-rows x BN
            if (BN == 128) {
                #pragma unroll
                for (int it = 0; it < 2; it++) {
                    int k = (tid >> 5) + it * 8;
                    int n = (tid & 31) * 4;
                    float4 bv = *reinterpret_cast<const float4*>(
                        &Bb[(long)(k0 + k) * ldb + nBase + n]);
                    *reinterpret_cast<float4*>(&Bs[k][n]) = bv;
                }
            } else {
                int k = tid >> 4;
                int n = (tid & 15) * 4;
                float4 bv = *reinterpret_cast<const float4*>(
                    &Bb[(long)(k0 + k) * ldb + nBase + n]);
                *reinterpret_cast<float4*>(&Bs[k][n]) = bv;
            }
        }
        __syncthreads();

        #pragma unroll
        for (int kk = 0; kk < BK; kk++) {
            float4 a4 = *reinterpret_cast<const float4*>(&As[kk][ty * 4]);
            u64 ap[4];
            ap[0] = pack2(a4.x, a4.x);
            ap[1] = pack2(a4.y, a4.y);
            ap[2] = pack2(a4.z, a4.z);
            ap[3] = pack2(a4.w, a4.w);

            u64 bp[TNH];
            {
                float4 b0 = *reinterpret_cast<const float4*>(&Bs[kk][tx * TN]);
                bp[0] = pack2(b0.x, b0.y);
                bp[1] = pack2(b0.z, b0.w);
                if (TN == 8) {
                    float4 b1 = *reinterpret_cast<const float4*>(&Bs[kk][tx * TN + 4]);
                    bp[2] = pack2(b1.x, b1.y);
                    bp[3] = pack2(b1.z, b1.w);
                }
            }
            #pragma unroll
            for (int i = 0; i < 4; i++)
                #pragma unroll
                for (int j = 0; j < TNH; j++)
                    ffma2(acc[i][j], ap[i], bp[j]);
        }
        __syncthreads();
    }

    // ---- store (float2 per pair) ----
    #pragma unroll
    for (int i = 0; i < 4; i++) {
        float* crow = Cb + (long)(ty * 4 + i) * ldc + tx * TN;
        #pragma unroll
        for (int j = 0; j < TNH; j++) {
            float2 v;
            asm("mov.b64 {%0, %1}, %2;" : "=f"(v.x), "=f"(v.y) : "l"(acc[i][j]));
            *reinterpret_cast<float2*>(crow + 2 * j) = v;
        }
    }
}

// ---------------- softmax over d (with S scaling folded in) ----------------
__device__ __forceinline__ float warpMaxf(float v) {
    #pragma unroll
    for (int o = 16; o > 0; o >>= 1) v = fmaxf(v, __shfl_xor_sync(0xffffffffu, v, o));
    return v;
}
__device__ __forceinline__ float warpSumf(float v) {
    #pragma unroll
    for (int o = 16; o > 0; o >>= 1) v += __shfl_xor_sync(0xffffffffu, v, o);
    return v;
}

__global__ void softmax_kernel() {
    int bh = blockIdx.x;
    int b = bh >> 7;                       // / H_
    float* row = g_scores + (long)bh * DC_;
    const float* Sb = g_S + b * DC_;
    int tid = threadIdx.x;                 // 128
    int lane = tid & 31, wid = tid >> 5;

    float v[4];
    float mx = -3.4e38f;
    #pragma unroll
    for (int i = 0; i < 4; i++) {
        int d = tid + i * 128;
        v[i] = row[d] * Sb[d];
        mx = fmaxf(mx, v[i]);
    }
    mx = warpMaxf(mx);
    __shared__ float sm[4], ss[4];
    if (lane == 0) sm[wid] = mx;
    __syncthreads();
    mx = fmaxf(fmaxf(sm[0], sm[1]), fmaxf(sm[2], sm[3]));

    float sum = 0.f;
    #pragma unroll
    for (int i = 0; i < 4; i++) {
        v[i] = expf(v[i] - mx);
        sum += v[i];
    }
    sum = warpSumf(sum);
    if (lane == 0) ss[wid] = sum;
    __syncthreads();
    sum = ss[0] + ss[1] + ss[2] + ss[3];
    float inv = 1.0f / sum;
    #pragma unroll
    for (int i = 0; i < 4; i++)
        row[tid + i * 128] = v[i] * inv;
}

// ---------------- split-K reduction for final GEMM ----------------
__global__ void reduce_split_kernel(float* __restrict__ out) {
    int i = blockIdx.x * 256 + threadIdx.x;   // B*DQ = 131072
    float s = 0.f;
    #pragma unroll
    for (int sp = 0; sp < SPLITS; sp++)
        s += g_split[(long)sp * (B_ * DQ_) + i];
    out[i] = s;
}

// ---------------- launch ----------------
extern "C" void kernel_launch(void* const* d_in, const int* in_sizes, int n_in,
                              void* d_out, int out_size) {
    const float* hidden_q   = (const float*)d_in[0];   // [B, DQ]
    const float* kv_c       = (const float*)d_in[1];   // [B, L, DC]
    const float* q_proj_w   = (const float*)d_in[2];   // [H*K, DQ]
    const float* w_kc_q     = (const float*)d_in[3];   // [H, K, DCQ]
    const float* w_kc_kv    = (const float*)d_in[4];   // [H, K, DC]
    const float* W_qr       = (const float*)d_in[5];   // [H, DCQ, R]
    const float* W_kr       = (const float*)d_in[6];   // [H, DC, R]
    const float* out_proj_w = (const float*)d_in[7];   // [DQ, H*K]
    float* out = (float*)d_out;

    float *p_kv, *p_qhk, *p_W2, *p_qr, *p_sc, *p_ctx, *p_lat, *p_split;
    cudaGetSymbolAddress((void**)&p_kv,    g_kv);
    cudaGetSymbolAddress((void**)&p_qhk,   g_qhk);
    cudaGetSymbolAddress((void**)&p_W2,    g_W2);
    cudaGetSymbolAddress((void**)&p_qr,    g_qr);
    cudaGetSymbolAddress((void**)&p_sc,    g_scores);
    cudaGetSymbolAddress((void**)&p_ctx,   g_ctx);
    cudaGetSymbolAddress((void**)&p_lat,   g_lat);
    cudaGetSymbolAddress((void**)&p_split, g_split);

    // 1. RoPE tables, then RoPE + S reduction
    rope_table_kernel<<<(L_ * DC_) / 256, 256>>>();
    rope_kernel<<<dim3(DC_ / 128, B_), 128>>>(kv_c);

    // 2. q_hk = hidden_q @ q_proj_w^T        [64, 16384] (NT)
    gemm2_kernel<128, true><<<dim3(HK_ / 128, 1, 1), 256>>>(
        hidden_q, q_proj_w, p_qhk,
        B_, HK_, DQ_, DQ_, DQ_, HK_, 0, 0, 0);

    // 3. W2[h] = w_kc_q[h] @ W_qr[h]         [128, 64] per head (NN)
    gemm2_kernel<64, false><<<dim3(1, 2, H_), 256>>>(
        w_kc_q, W_qr, p_W2,
        K_, R_, DCQ_, DCQ_, R_, R_,
        (long)K_ * DCQ_, (long)DCQ_ * R_, (long)K_ * R_);

    // 4. q_r[b,h,:] = q_hk[b,h,:] @ W2[h]    [64, 64] per head (NN)
    gemm2_kernel<64, false><<<dim3(1, 1, H_), 256>>>(
        p_qhk, p_W2, p_qr,
        B_, R_, K_, HK_, R_, H_ * R_,
        (long)K_, (long)K_ * R_, (long)R_);

    // 5. T[b,h,d] = q_r[b,h,:] . W_kr[h,d,:] [64, 512] per head (NT) -> scores
    gemm2_kernel<128, true><<<dim3(DC_ / 128, 1, H_), 256>>>(
        p_qr, W_kr, p_sc,
        B_, DC_, R_, H_ * R_, R_, H_ * DC_,
        (long)R_, (long)DC_ * R_, (long)DC_);

    // 6. softmax over d, with scores *= S[b,d] folded in (attn in place)
    softmax_kernel<<<B_ * H_, 128>>>();

    // 7. ctx_c[b] = attn[b] @ kv[b]          [128, 512] per batch (NN)
    gemm2_kernel<128, false><<<dim3(DC_ / 128, H_ / 64, B_), 256>>>(
        p_sc, p_kv, p_ctx,
        H_, DC_, L_, DC_, DC_, DC_,
        (long)H_ * DC_, (long)L_ * DC_, (long)H_ * DC_);

    // 8. ctx_lat[b,h,:] = ctx_c[b,h,:] @ w_kc_kv[h]^T  [64, 128] per head (NT)
    gemm2_kernel<128, true><<<dim3(K_ / 128, 1, H_), 256>>>(
        p_ctx, w_kc_kv, p_lat,
        B_, K_, DC_, H_ * DC_, DC_, HK_,
        (long)DC_, (long)K_ * DC_, (long)K_);

    // 9. out = ctx_lat @ out_proj_w^T  — deterministic split-K (16 chunks of 1024)
    gemm2_kernel<128, true><<<dim3(DQ_ / 128, 1, SPLITS), 256>>>(
        p_lat, out_proj_w, p_split,
        B_, DQ_, HK_ / SPLITS, HK_, HK_, DQ_,
        (long)(HK_ / SPLITS), (long)(HK_ / SPLITS), (long)B_ * DQ_);

    reduce_split_kernel<<<(B_ * DQ_) / 256, 256>>>(out);
}

// round 8
// speedup vs baseline: 1.6181x; 1.4416x over previous
#include <cuda_runtime.h>
#include <math.h>

// Problem constants
constexpr int B_   = 64;
constexpr int L_   = 512;
constexpr int DQ_  = 2048;
constexpr int H_   = 128;
constexpr int K_   = 128;
constexpr int DC_  = 512;
constexpr int DCQ_ = 1536;
constexpr int R_   = 64;
constexpr int HK_  = H_ * K_;      // 16384
constexpr int SPLITS = 16;         // step 9 split-K
constexpr int QSPLIT = 4;          // step 2 split-K

typedef unsigned long long u64;

// ---------------- scratch (no cudaMalloc allowed) ----------------
__device__ float g_sin[L_ * DC_];
__device__ float g_cos[L_ * DC_];
__device__ float g_kv[B_ * L_ * DC_];      // roped kv
__device__ float g_S[B_ * DC_];            // sum over l of kv
__device__ float g_qhk[B_ * HK_];          // [B, H*K]
__device__ float g_W2[H_ * K_ * R_];       // fused w_kc_q @ W_qr per head
__device__ float g_qr[B_ * H_ * R_];       // [B, H, R]
__device__ float g_scores[B_ * H_ * DC_];  // scores -> attn (in place)
__device__ float g_ctx[B_ * H_ * DC_];     // ctx_c
__device__ float g_lat[B_ * HK_];          // ctx_lat
__device__ float g_split[SPLITS * B_ * DQ_];
__device__ float g_qsplit[QSPLIT * B_ * HK_];

// ---------------- f32x2 packed helpers ----------------
__device__ __forceinline__ u64 pack2(float lo, float hi) {
    u64 r; asm("mov.b64 %0, {%1, %2};" : "=l"(r) : "f"(lo), "f"(hi)); return r;
}
__device__ __forceinline__ void ffma2(u64& d, u64 a, u64 b) {
    asm("fma.rn.f32x2 %0, %1, %2, %0;" : "+l"(d) : "l"(a), "l"(b));
}
__device__ __forceinline__ float2 unpack2(u64 v) {
    float2 r; asm("mov.b64 {%0, %1}, %2;" : "=f"(r.x), "=f"(r.y) : "l"(v)); return r;
}

// ---------------- RoPE tables ----------------
__global__ void rope_table_kernel() {
    int idx = blockIdx.x * 256 + threadIdx.x;      // L*DC = 262144
    int l = idx / DC_;
    int d = idx % DC_;
    float expo = (float)(d & ~1) / (float)DC_;     // 2*(d/2)/DC
    float invf = expf(-expo * 9.210340371976184f); // ln(10000)
    float ang = (float)l * invf;
    g_sin[idx] = sinf(ang);
    g_cos[idx] = cosf(ang);
}

// ---------------- RoPE + column sum S ----------------
__global__ void rope_kernel(const float* __restrict__ kv_c) {
    int d = blockIdx.x * 128 + threadIdx.x;
    int b = blockIdx.y;
    const float* src = kv_c + (long)b * L_ * DC_;
    float* dst = g_kv + (long)b * L_ * DC_;
    int d2 = (d < DC_ / 2) ? d + DC_ / 2 : d - DC_ / 2;
    float sign = (d < DC_ / 2) ? -1.f : 1.f;
    float s = 0.f;
    for (int l = 0; l < L_; l++) {
        float x = src[l * DC_ + d];
        float y = src[l * DC_ + d2];
        float v = x * g_cos[l * DC_ + d] + sign * y * g_sin[l * DC_ + d];
        dst[l * DC_ + d] = v;
        s += v;
    }
    g_S[b * DC_ + d] = s;
}

// ================= double-buffered batched SGEMM, FFMA2 core =================
// C[z][M,N] = A[z][M,Kd] * B[z]  (TRANSB: B is [N,Kd]; else [Kd,N]).
// BM=64, BK=16, 128 threads, microtile 8 x TN per thread (TN = BN/16).
// Requirements (hold by construction): M%64==0, N%BN==0, Kd%16==0, 16B-aligned.
template <int BN, bool TRANSB>
__global__ void __launch_bounds__(128, 4) gemm3_kernel(
    const float* __restrict__ A, const float* __restrict__ Bm, float* __restrict__ C,
    int M, int N, int Kd, int lda, int ldb, int ldc,
    long sA, long sB, long sC)
{
    constexpr int BM = 64, BK = 16;
    constexpr int TN  = BN / 16;       // 8 or 4
    constexpr int TNH = TN / 2;        // u64 pairs along n
    constexpr int ASTR = 70;           // padded (even, conflict-free transpose)
    constexpr int NB = TRANSB ? (BN == 128 ? 4 : 2) : (BN == 128 ? 4 : 2);

    __shared__ float As[2][BK][ASTR];
    __shared__ float Bs[2][BK][BN];

    const int tid = threadIdx.x;
    const int tx = tid & 15;           // n group
    const int ty = tid >> 4;           // m group (8 rows each)

    const float* Ab = A + (long)blockIdx.z * sA + (long)blockIdx.y * BM * lda;
    const float* Bb = Bm + (long)blockIdx.z * sB;
    const int nBase = blockIdx.x * BN;
    float* Cb = C + (long)blockIdx.z * sC + (long)blockIdx.y * BM * ldc + nBase;

    // A staging mapping: 64 rows x 16 k = 256 float4, 2 per thread
    const int aRow = tid >> 2;         // 0..31 (+32)
    const int aKq  = (tid & 3) * 4;    // 0,4,8,12

    float4 aReg[2];
    float4 bReg[NB];

    u64 acc[8][TNH];
    #pragma unroll
    for (int i = 0; i < 8; i++)
        #pragma unroll
        for (int j = 0; j < TNH; j++) acc[i][j] = 0ull;

    const int T = Kd / BK;

    // ---- tile load (global -> regs) ----
    auto LDG_TILE = [&](int k0) {
        aReg[0] = *reinterpret_cast<const float4*>(&Ab[(long)aRow * lda + k0 + aKq]);
        aReg[1] = *reinterpret_cast<const float4*>(&Ab[(long)(aRow + 32) * lda + k0 + aKq]);
        if (TRANSB) {
            if (BN == 128) {
                int n = tid;
                #pragma unroll
                for (int it = 0; it < 4; it++)
                    bReg[it] = *reinterpret_cast<const float4*>(
                        &Bb[(long)(nBase + n) * ldb + k0 + it * 4]);
            } else {
                int n = tid & 63;
                int kb = (tid >> 6) * 8;
                #pragma unroll
                for (int it = 0; it < 2; it++)
                    bReg[it] = *reinterpret_cast<const float4*>(
                        &Bb[(long)(nBase + n) * ldb + k0 + kb + it * 4]);
            }
        } else {
            int k = tid >> 3;
            #pragma unroll
            for (int it = 0; it < NB; it++)
                bReg[it] = *reinterpret_cast<const float4*>(
                    &Bb[(long)(k0 + k) * ldb + nBase + ((tid & 7) + it * 8) * 4]);
        }
    };
    // ---- tile store (regs -> smem) ----
    auto STS_TILE = [&](int buf) {
        #pragma unroll
        for (int r = 0; r < 2; r++) {
            int m = aRow + r * 32;
            As[buf][aKq + 0][m] = (r ? aReg[1].x : aReg[0].x);
            As[buf][aKq + 1][m] = (r ? aReg[1].y : aReg[0].y);
            As[buf][aKq + 2][m] = (r ? aReg[1].z : aReg[0].z);
            As[buf][aKq + 3][m] = (r ? aReg[1].w : aReg[0].w);
        }
        if (TRANSB) {
            if (BN == 128) {
                int n = tid;
                #pragma unroll
                for (int it = 0; it < 4; it++) {
                    Bs[buf][it * 4 + 0][n] = bReg[it].x;
                    Bs[buf][it * 4 + 1][n] = bReg[it].y;
                    Bs[buf][it * 4 + 2][n] = bReg[it].z;
                    Bs[buf][it * 4 + 3][n] = bReg[it].w;
                }
            } else {
                int n = tid & 63;
                int kb = (tid >> 6) * 8;
                #pragma unroll
                for (int it = 0; it < 2; it++) {
                    Bs[buf][kb + it * 4 + 0][n] = bReg[it].x;
                    Bs[buf][kb + it * 4 + 1][n] = bReg[it].y;
                    Bs[buf][kb + it * 4 + 2][n] = bReg[it].z;
                    Bs[buf][kb + it * 4 + 3][n] = bReg[it].w;
                }
            }
        } else {
            int k = tid >> 3;
            #pragma unroll
            for (int it = 0; it < NB; it++)
                *reinterpret_cast<float4*>(&Bs[buf][k][((tid & 7) + it * 8) * 4]) = bReg[it];
        }
    };

    LDG_TILE(0);
    STS_TILE(0);
    __syncthreads();

    for (int t = 0; t < T; t++) {
        const int buf = t & 1;
        if (t + 1 < T) LDG_TILE((t + 1) * BK);

        #pragma unroll
        for (int kk = 0; kk < BK; kk++) {
            // a: 8 floats, duplicated into f32x2
            const float2* ap = reinterpret_cast<const float2*>(&As[buf][kk][ty * 8]);
            u64 ad[8];
            #pragma unroll
            for (int p = 0; p < 4; p++) {
                float2 av = ap[p];
                ad[2 * p + 0] = pack2(av.x, av.x);
                ad[2 * p + 1] = pack2(av.y, av.y);
            }
            // b: TN floats read directly as u64 pairs
            const u64* bq = reinterpret_cast<const u64*>(&Bs[buf][kk][tx * TN]);
            u64 bp[TNH];
            #pragma unroll
            for (int j = 0; j < TNH; j++) bp[j] = bq[j];

            #pragma unroll
            for (int i = 0; i < 8; i++)
                #pragma unroll
                for (int j = 0; j < TNH; j++)
                    ffma2(acc[i][j], ad[i], bp[j]);
        }

        if (t + 1 < T) STS_TILE(1 - buf);
        __syncthreads();
    }

    // ---- epilogue: float4 stores ----
    #pragma unroll
    for (int i = 0; i < 8; i++) {
        float* crow = Cb + (long)(ty * 8 + i) * ldc + tx * TN;
        #pragma unroll
        for (int q = 0; q < TNH / 2; q++) {
            float2 lo = unpack2(acc[i][2 * q + 0]);
            float2 hi = unpack2(acc[i][2 * q + 1]);
            float4 v = make_float4(lo.x, lo.y, hi.x, hi.y);
            *reinterpret_cast<float4*>(crow + 4 * q) = v;
        }
        if (TNH == 1) {  // BN=64 edge: single float2
            float2 lo = unpack2(acc[i][0]);
            *reinterpret_cast<float2*>(crow) = lo;
        }
    }
}

// ---------------- softmax over d (with S scaling folded in) ----------------
__device__ __forceinline__ float warpMaxf(float v) {
    #pragma unroll
    for (int o = 16; o > 0; o >>= 1) v = fmaxf(v, __shfl_xor_sync(0xffffffffu, v, o));
    return v;
}
__device__ __forceinline__ float warpSumf(float v) {
    #pragma unroll
    for (int o = 16; o > 0; o >>= 1) v += __shfl_xor_sync(0xffffffffu, v, o);
    return v;
}

__global__ void softmax_kernel() {
    int bh = blockIdx.x;
    int b = bh >> 7;                       // / H_
    float* row = g_scores + (long)bh * DC_;
    const float* Sb = g_S + b * DC_;
    int tid = threadIdx.x;                 // 128
    int lane = tid & 31, wid = tid >> 5;

    float v[4];
    float mx = -3.4e38f;
    #pragma unroll
    for (int i = 0; i < 4; i++) {
        int d = tid + i * 128;
        v[i] = row[d] * Sb[d];
        mx = fmaxf(mx, v[i]);
    }
    mx = warpMaxf(mx);
    __shared__ float sm[4], ss[4];
    if (lane == 0) sm[wid] = mx;
    __syncthreads();
    mx = fmaxf(fmaxf(sm[0], sm[1]), fmaxf(sm[2], sm[3]));

    float sum = 0.f;
    #pragma unroll
    for (int i = 0; i < 4; i++) {
        v[i] = expf(v[i] - mx);
        sum += v[i];
    }
    sum = warpSumf(sum);
    if (lane == 0) ss[wid] = sum;
    __syncthreads();
    sum = ss[0] + ss[1] + ss[2] + ss[3];
    float inv = 1.0f / sum;
    #pragma unroll
    for (int i = 0; i < 4; i++)
        row[tid + i * 128] = v[i] * inv;
}

// ---------------- split-K reductions ----------------
__global__ void reduce_split_kernel(float* __restrict__ out) {
    int i = blockIdx.x * 256 + threadIdx.x;   // B*DQ = 131072
    float s = 0.f;
    #pragma unroll
    for (int sp = 0; sp < SPLITS; sp++)
        s += g_split[(long)sp * (B_ * DQ_) + i];
    out[i] = s;
}

__global__ void reduce_qsplit_kernel() {
    int i = blockIdx.x * 256 + threadIdx.x;   // B*HK = 1048576
    float s = 0.f;
    #pragma unroll
    for (int sp = 0; sp < QSPLIT; sp++)
        s += g_qsplit[(long)sp * (B_ * HK_) + i];
    g_qhk[i] = s;
}

// ---------------- launch ----------------
extern "C" void kernel_launch(void* const* d_in, const int* in_sizes, int n_in,
                              void* d_out, int out_size) {
    const float* hidden_q   = (const float*)d_in[0];   // [B, DQ]
    const float* kv_c       = (const float*)d_in[1];   // [B, L, DC]
    const float* q_proj_w   = (const float*)d_in[2];   // [H*K, DQ]
    const float* w_kc_q     = (const float*)d_in[3];   // [H, K, DCQ]
    const float* w_kc_kv    = (const float*)d_in[4];   // [H, K, DC]
    const float* W_qr       = (const float*)d_in[5];   // [H, DCQ, R]
    const float* W_kr       = (const float*)d_in[6];   // [H, DC, R]
    const float* out_proj_w = (const float*)d_in[7];   // [DQ, H*K]
    float* out = (float*)d_out;

    float *p_kv, *p_qhk, *p_W2, *p_qr, *p_sc, *p_ctx, *p_lat, *p_split, *p_qsplit;
    cudaGetSymbolAddress((void**)&p_kv,     g_kv);
    cudaGetSymbolAddress((void**)&p_qhk,    g_qhk);
    cudaGetSymbolAddress((void**)&p_W2,     g_W2);
    cudaGetSymbolAddress((void**)&p_qr,     g_qr);
    cudaGetSymbolAddress((void**)&p_sc,     g_scores);
    cudaGetSymbolAddress((void**)&p_ctx,    g_ctx);
    cudaGetSymbolAddress((void**)&p_lat,    g_lat);
    cudaGetSymbolAddress((void**)&p_split,  g_split);
    cudaGetSymbolAddress((void**)&p_qsplit, g_qsplit);

    // 1. RoPE tables, then RoPE + S reduction
    rope_table_kernel<<<(L_ * DC_) / 256, 256>>>();
    rope_kernel<<<dim3(DC_ / 128, B_), 128>>>(kv_c);

    // 2. q_hk = hidden_q @ q_proj_w^T   [64,16384] (NT), split-K 4 -> 512 blocks
    gemm3_kernel<128, true><<<dim3(HK_ / 128, 1, QSPLIT), 128>>>(
        hidden_q, q_proj_w, p_qsplit,
        B_, HK_, DQ_ / QSPLIT, DQ_, DQ_, HK_,
        (long)(DQ_ / QSPLIT), (long)(DQ_ / QSPLIT), (long)B_ * HK_);
    reduce_qsplit_kernel<<<(B_ * HK_) / 256, 256>>>();

    // 3. W2[h] = w_kc_q[h] @ W_qr[h]    [128,64] per head (NN) -> 256 blocks
    gemm3_kernel<64, false><<<dim3(1, 2, H_), 128>>>(
        w_kc_q, W_qr, p_W2,
        K_, R_, DCQ_, DCQ_, R_, R_,
        (long)K_ * DCQ_, (long)DCQ_ * R_, (long)K_ * R_);

    // 4. q_r[b,h,:] = q_hk[b,h,:] @ W2[h]  [64,64] per head (NN)
    gemm3_kernel<64, false><<<dim3(1, 1, H_), 128>>>(
        p_qhk, p_W2, p_qr,
        B_, R_, K_, HK_, R_, H_ * R_,
        (long)K_, (long)K_ * R_, (long)R_);

    // 5. scores[b,h,d] = q_r[b,h,:] . W_kr[h,d,:]  [64,512] per head (NT)
    gemm3_kernel<128, true><<<dim3(DC_ / 128, 1, H_), 128>>>(
        p_qr, W_kr, p_sc,
        B_, DC_, R_, H_ * R_, R_, H_ * DC_,
        (long)R_, (long)DC_ * R_, (long)DC_);

    // 6. softmax over d, with scores *= S[b,d] folded in (attn in place)
    softmax_kernel<<<B_ * H_, 128>>>();

    // 7. ctx_c[b] = attn[b] @ kv[b]   [128,512] per batch (NN) -> 512 blocks
    gemm3_kernel<128, false><<<dim3(DC_ / 128, H_ / 64, B_), 128>>>(
        p_sc, p_kv, p_ctx,
        H_, DC_, L_, DC_, DC_, DC_,
        (long)H_ * DC_, (long)L_ * DC_, (long)H_ * DC_);

    // 8. ctx_lat[b,h,:] = ctx_c[b,h,:] @ w_kc_kv[h]^T  [64,128] per head (NT)
    gemm3_kernel<64, true><<<dim3(K_ / 64, 1, H_), 128>>>(
        p_ctx, w_kc_kv, p_lat,
        B_, K_, DC_, H_ * DC_, DC_, HK_,
        (long)DC_, (long)K_ * DC_, (long)K_);

    // 9. out = ctx_lat @ out_proj_w^T — split-K 16 -> 256 blocks
    gemm3_kernel<128, true><<<dim3(DQ_ / 128, 1, SPLITS), 128>>>(
        p_lat, out_proj_w, p_split,
        B_, DQ_, HK_ / SPLITS, HK_, HK_, DQ_,
        (long)(HK_ / SPLITS), (long)(HK_ / SPLITS), (long)B_ * DQ_);

    reduce_split_kernel<<<(B_ * DQ_) / 256, 256>>>(out);
}